// round 1
// baseline (speedup 1.0000x reference)
#include <cuda_runtime.h>
#include <cuda_bf16.h>
#include <cstdint>

// ---------------------------------------------------------------------------
// InteractionPPBlock (DimeNet++) — round 1: correct baseline, fp32 FFMA GEMMs
//   E=200000, T=2000000, H=256, INT=64, BAS=8, NRAD=6, SBF=42, NB=1, NA=2
// ---------------------------------------------------------------------------

#define H 256
#define INTC 64
#define SBF_DIM 42
#define NRAD 6
#define BAS 8

#define MAXE 200704          // padded E
#define MAXE_H ((size_t)MAXE * H)
#define MAXE_I ((size_t)MAXE * INTC)

// scratch (device globals — no cudaMalloc allowed)
__device__ float g_buf0[MAXE_H];   // ping
__device__ float g_buf1[MAXE_H];   // pong
__device__ float g_buf2[MAXE_H];   // pang
__device__ float g_down[MAXE_I];
__device__ float g_agg[MAXE_I];
__device__ float g_Wr[NRAD * H];   // W_rbf1 @ W_rbf2  [6,256]

__device__ __forceinline__ float silu(float v) {
    return v / (1.0f + __expf(-v));
}

// ---------------------------------------------------------------------------
// Tiny: Wr = W_rbf1[6,8] @ W_rbf2[8,256]
// ---------------------------------------------------------------------------
__global__ void wr_kernel(const float* __restrict__ W1, const float* __restrict__ W2) {
    int c = threadIdx.x;  // 256
    #pragma unroll
    for (int k = 0; k < NRAD; k++) {
        float v = 0.f;
        #pragma unroll
        for (int j = 0; j < BAS; j++) v += W1[k * BAS + j] * W2[j * H + c];
        g_Wr[k * H + c] = v;
    }
}

// ---------------------------------------------------------------------------
// rbf_e[e,c] = sum_k rbf[e,k] * Wr[k,c]   (64 edges per block, 256 threads)
// ---------------------------------------------------------------------------
__global__ void __launch_bounds__(256) rbfe_kernel(
    const float* __restrict__ rbf, float* __restrict__ out, int E) {
    __shared__ float srbf[64 * NRAD];
    const int tid = threadIdx.x;
    const int e0 = blockIdx.x * 64;
    float w[NRAD];
    #pragma unroll
    for (int k = 0; k < NRAD; k++) w[k] = g_Wr[k * H + tid];
    for (int i = tid; i < 64 * NRAD; i += 256) {
        int e = e0 + i / NRAD;
        srbf[i] = (e < E) ? rbf[(size_t)e * NRAD + (i % NRAD)] : 0.f;
    }
    __syncthreads();
    for (int r = 0; r < 64; r++) {
        int e = e0 + r;
        if (e >= E) break;
        float v = 0.f;
        #pragma unroll
        for (int k = 0; k < NRAD; k++) v += w[k] * srbf[r * NRAD + k];
        out[(size_t)e * H + tid] = v;
    }
}

// ---------------------------------------------------------------------------
// General SGEMM: C = epi(A[M,K] @ W[K,N])
//   epi: v = acc (+ bias[col]); v = silu(v); v *= mul[r,c]; v += add[r,c]
//   BM=BN=128, BK=8, 256 threads, 8x8 per-thread tile
// ---------------------------------------------------------------------------
#define BM 128
#define BN 128
#define BK 8
#define TM 8
#define TN 8

__global__ void __launch_bounds__(256) gemm_silu(
    const float* __restrict__ A, const float* __restrict__ W,
    const float* __restrict__ bias, const float* __restrict__ mul,
    const float* __restrict__ add, float* __restrict__ C,
    int M, int N, int K) {
    __shared__ float As[BK][BM];
    __shared__ float Bs[BK][BN];

    const int tid = threadIdx.x;
    const int rowBase = blockIdx.x * BM;
    const int colBase = blockIdx.y * BN;

    const int a_r = tid >> 1;            // 0..127
    const int a_c = (tid & 1) * 4;       // 0 or 4
    const int b_r = tid >> 5;            // 0..7
    const int b_c = (tid & 31) * 4;      // 0..124

    const int tr = (tid / 16) * TM;
    const int tc = (tid % 16) * TN;

    float acc[TM][TN];
    #pragma unroll
    for (int i = 0; i < TM; i++)
        #pragma unroll
        for (int j = 0; j < TN; j++) acc[i][j] = 0.f;

    const int gArow = rowBase + a_r;
    const bool aValid = gArow < M;
    const float* Aptr = A + (size_t)gArow * K + a_c;
    const int gBcol = colBase + b_c;
    const bool bValid = gBcol < N;

    for (int k0 = 0; k0 < K; k0 += BK) {
        float4 av = make_float4(0.f, 0.f, 0.f, 0.f);
        if (aValid) av = *reinterpret_cast<const float4*>(Aptr + k0);
        As[a_c + 0][a_r] = av.x;
        As[a_c + 1][a_r] = av.y;
        As[a_c + 2][a_r] = av.z;
        As[a_c + 3][a_r] = av.w;

        float4 bv = make_float4(0.f, 0.f, 0.f, 0.f);
        if (bValid) bv = *reinterpret_cast<const float4*>(W + (size_t)(k0 + b_r) * N + gBcol);
        *reinterpret_cast<float4*>(&Bs[b_r][b_c]) = bv;
        __syncthreads();

        #pragma unroll
        for (int k = 0; k < BK; k++) {
            float ra[TM], rb[TN];
            #pragma unroll
            for (int i = 0; i < TM; i++) ra[i] = As[k][tr + i];
            #pragma unroll
            for (int j = 0; j < TN; j++) rb[j] = Bs[k][tc + j];
            #pragma unroll
            for (int i = 0; i < TM; i++)
                #pragma unroll
                for (int j = 0; j < TN; j++) acc[i][j] += ra[i] * rb[j];
        }
        __syncthreads();
    }

    #pragma unroll
    for (int i = 0; i < TM; i++) {
        const int gr = rowBase + tr + i;
        if (gr >= M) continue;
        #pragma unroll
        for (int j = 0; j < TN; j++) {
            const int gc = colBase + tc + j;
            if (gc >= N) continue;
            float v = acc[i][j];
            if (bias) v += bias[gc];
            v = silu(v);
            const size_t idx = (size_t)gr * N + gc;
            if (mul) v *= mul[idx];
            if (add) v += add[idx];
            C[idx] = v;
        }
    }
}

// ---------------------------------------------------------------------------
// Triplet scatter:  agg[idx_ji] += (sbf @ W_sbf1 @ W_sbf2) * down[idx_kj]
//   8 triplets / block, 64 threads (channels) per triplet
// ---------------------------------------------------------------------------
#define SC_TPB 8
__global__ void __launch_bounds__(512) scatter_kernel(
    const float* __restrict__ sbf, const int* __restrict__ idx_kj,
    const int* __restrict__ idx_ji, const float* __restrict__ W1,  // [42,8]
    const float* __restrict__ W2,                                   // [8,64]
    int T) {
    __shared__ float W1s[SBF_DIM * BAS];
    __shared__ float W2s[BAS * INTC];
    __shared__ float sbfs[SC_TPB][SBF_DIM];
    __shared__ float bs[SC_TPB][BAS];

    const int tid = threadIdx.x;
    for (int i = tid; i < SBF_DIM * BAS; i += 512) W1s[i] = W1[i];
    for (int i = tid; i < BAS * INTC; i += 512) W2s[i] = W2[i];

    const int t = tid >> 6;       // triplet within block
    const int c = tid & 63;       // channel
    const long tri = (long)blockIdx.x * SC_TPB + t;
    const bool valid = tri < (long)T;

    if (valid && c < SBF_DIM) sbfs[t][c] = sbf[tri * SBF_DIM + c];
    __syncthreads();

    if (valid && c < BAS) {
        float b = 0.f;
        #pragma unroll
        for (int j = 0; j < SBF_DIM; j++) b += sbfs[t][j] * W1s[j * BAS + c];
        bs[t][c] = b;
    }
    __syncthreads();

    if (valid) {
        float s = 0.f;
        #pragma unroll
        for (int k = 0; k < BAS; k++) s += bs[t][k] * W2s[k * INTC + c];
        const int kj = idx_kj[tri];
        const int ji = idx_ji[tri];
        const float m = s * g_down[(size_t)kj * INTC + c];
        atomicAdd(&g_agg[(size_t)ji * INTC + c], m);
    }
}

// ---------------------------------------------------------------------------
// Host orchestration
// ---------------------------------------------------------------------------
static inline void launch_gemm(const float* A, const float* W, const float* bias,
                               const float* mul, const float* add, float* C,
                               int M, int N, int K) {
    dim3 grid((M + BM - 1) / BM, (N + BN - 1) / BN);
    gemm_silu<<<grid, 256>>>(A, W, bias, mul, add, C, M, N, K);
}

extern "C" void kernel_launch(void* const* d_in, const int* in_sizes, int n_in,
                              void* d_out, int out_size) {
    const float* x      = (const float*)d_in[0];
    const float* rbf    = (const float*)d_in[1];
    const float* sbf    = (const float*)d_in[2];
    const int*   idx_kj = (const int*)d_in[3];
    const int*   idx_ji = (const int*)d_in[4];
    const float* W_rbf1 = (const float*)d_in[5];
    const float* W_rbf2 = (const float*)d_in[6];
    const float* W_sbf1 = (const float*)d_in[7];
    const float* W_sbf2 = (const float*)d_in[8];
    const float* W_kj   = (const float*)d_in[9];
    const float* b_kj   = (const float*)d_in[10];
    const float* W_ji   = (const float*)d_in[11];
    const float* b_ji   = (const float*)d_in[12];
    const float* W_down = (const float*)d_in[13];
    const float* W_up   = (const float*)d_in[14];
    const float* rb_W1  = (const float*)d_in[15];
    const float* rb_b1  = (const float*)d_in[16];
    const float* rb_W2  = (const float*)d_in[17];
    const float* rb_b2  = (const float*)d_in[18];
    const float* W_lin  = (const float*)d_in[19];
    const float* b_lin  = (const float*)d_in[20];
    const float* ra_W1  = (const float*)d_in[21];
    const float* ra_b1  = (const float*)d_in[22];
    const float* ra_W2  = (const float*)d_in[23];
    const float* ra_b2  = (const float*)d_in[24];

    const int E = in_sizes[0] / H;
    const int T = in_sizes[3];
    float* out = (float*)d_out;

    float *buf0, *buf1, *buf2, *down, *agg;
    cudaGetSymbolAddress((void**)&buf0, g_buf0);
    cudaGetSymbolAddress((void**)&buf1, g_buf1);
    cudaGetSymbolAddress((void**)&buf2, g_buf2);
    cudaGetSymbolAddress((void**)&down, g_down);
    cudaGetSymbolAddress((void**)&agg,  g_agg);

    // 0) basis precompute + rbf embedding
    wr_kernel<<<1, 256>>>(W_rbf1, W_rbf2);
    rbfe_kernel<<<(E + 63) / 64, 256>>>(rbf, buf1, E);                 // buf1 = rbf_e [E,H]

    // 1) x_ji = silu(x @ W_ji + b_ji)
    launch_gemm(x, W_ji, b_ji, nullptr, nullptr, buf0, E, H, H);       // buf0 = x_ji

    // 2) t = silu(x @ W_kj + b_kj) * rbf_e
    launch_gemm(x, W_kj, b_kj, buf1, nullptr, buf2, E, H, H);          // buf2 = t

    // 3) down = silu(t @ W_down)   [E,64]
    launch_gemm(buf2, W_down, nullptr, nullptr, nullptr, down, E, INTC, H);

    // 4) agg = segment_sum( down[idx_kj] * (sbf@Wsbf1@Wsbf2), idx_ji )
    cudaMemsetAsync(agg, 0, (size_t)E * INTC * sizeof(float));
    scatter_kernel<<<(T + SC_TPB - 1) / SC_TPB, 512>>>(sbf, idx_kj, idx_ji,
                                                       W_sbf1, W_sbf2, T);

    // 5) h0 = x_ji + silu(agg @ W_up)
    launch_gemm(agg, W_up, nullptr, nullptr, buf0, buf2, E, H, INTC);  // buf2 = h0

    // 6) residual-before (NB=1): h1 = h0 + silu(silu(h0@rbW1+b1)@rbW2+b2)
    launch_gemm(buf2, rb_W1, rb_b1, nullptr, nullptr, buf1, E, H, H);  // buf1 = u
    launch_gemm(buf1, rb_W2, rb_b2, nullptr, buf2, buf0, E, H, H);     // buf0 = h1

    // 7) h2 = silu(h1 @ W_lin + b_lin) + x
    launch_gemm(buf0, W_lin, b_lin, nullptr, x, buf2, E, H, H);        // buf2 = h2

    // 8) residual-after #0
    launch_gemm(buf2, ra_W1, ra_b1, nullptr, nullptr, buf1, E, H, H);
    launch_gemm(buf1, ra_W2, ra_b2, nullptr, buf2, buf0, E, H, H);     // buf0 = h3

    // 9) residual-after #1 -> final output
    const float* ra_W1b = ra_W1 + (size_t)H * H;
    const float* ra_b1b = ra_b1 + H;
    const float* ra_W2b = ra_W2 + (size_t)H * H;
    const float* ra_b2b = ra_b2 + H;
    launch_gemm(buf0, ra_W1b, ra_b1b, nullptr, nullptr, buf1, E, H, H);
    launch_gemm(buf1, ra_W2b, ra_b2b, nullptr, buf0, out, E, H, H);
}